// round 2
// baseline (speedup 1.0000x reference)
#include <cuda_runtime.h>
#include <cuda_bf16.h>

// DConv: per-channel cyclic shift (on 1-padded 162x162 grid) followed by 3x3
// conv (pad 1) and center crop. Crop cancels conv padding, so:
//   out[b,co,oy,ox] = sum_{ci,ky,kx} w[co,ci,ky,kx] * xs[b,ci,oy+ky,ox+kx]
// with xs(i,j) = x[p-1,q-1] if p,q in [1,160] else 0,
//   p = (i - dy[ci%5]) mod 162, q = (j - dx[ci%5]) mod 162,
//   dy = {0,0,1,0,-1}, dx = {0,1,0,-1,0}.

#define TILE_H 32
#define TILE_W 32
#define CO_PER 8
#define SM_STRIDE 35   // (TILE_W+2)=34 padded to 35: conflict-free access pattern

__global__ __launch_bounds__(256, 2)
void dconv_kernel(const float* __restrict__ x,
                  const float* __restrict__ w,
                  float* __restrict__ out) {
    __shared__ float xs[(TILE_H + 2) * SM_STRIDE];
    __shared__ float ws[CO_PER * 9];

    const int tid = threadIdx.x;
    const int ox0 = blockIdx.x * TILE_W;
    const int oy0 = blockIdx.y * TILE_H;
    const int bz  = blockIdx.z;           // b * 8 + co_group
    const int b   = bz >> 3;
    const int co0 = (bz & 7) * CO_PER;

    const int tw = tid & 7;    // 0..7  -> 4 cols each
    const int th = tid >> 3;   // 0..31 -> row

    float acc[CO_PER][4];
#pragma unroll
    for (int c = 0; c < CO_PER; ++c)
#pragma unroll
        for (int p = 0; p < 4; ++p) acc[c][p] = 0.0f;

    const float* xb = x + (size_t)b * 64 * 160 * 160;

    for (int ci = 0; ci < 64; ++ci) {
        const int cm = ci % 5;
        const int dy = (cm == 2) ? 1 : ((cm == 4) ? -1 : 0);
        const int dx = (cm == 1) ? 1 : ((cm == 3) ? -1 : 0);
        const float* xc = xb + (size_t)ci * 160 * 160;

        // Stage shifted tile (TILE_H+2) x (TILE_W+2) into smem.
#pragma unroll
        for (int e = tid; e < (TILE_H + 2) * (TILE_W + 2); e += 256) {
            const int ti = e / (TILE_W + 2);
            const int tj = e % (TILE_W + 2);
            int p = oy0 + ti - dy;             // in [-1, 162]
            int q = ox0 + tj - dx;
            if (p < 0) p += 162; else if (p >= 162) p -= 162;
            if (q < 0) q += 162; else if (q >= 162) q -= 162;
            float v = 0.0f;
            if (p >= 1 && p <= 160 && q >= 1 && q <= 160)
                v = xc[(p - 1) * 160 + (q - 1)];
            xs[ti * SM_STRIDE + tj] = v;
        }
        // Stage weights for this ci: w[co0..co0+7][ci][0..8]
        if (tid < CO_PER * 9) {
            const int c = tid / 9, k = tid % 9;
            ws[tid] = w[((size_t)(co0 + c) * 64 + ci) * 9 + k];
        }
        __syncthreads();

        // Each thread: 3 rows x 6 cols of xs -> 4 output pixels.
        float xv[3][6];
#pragma unroll
        for (int r = 0; r < 3; ++r)
#pragma unroll
            for (int c2 = 0; c2 < 6; ++c2)
                xv[r][c2] = xs[(th + r) * SM_STRIDE + tw * 4 + c2];

#pragma unroll
        for (int c = 0; c < CO_PER; ++c) {
            float wr[9];
#pragma unroll
            for (int k = 0; k < 9; ++k) wr[k] = ws[c * 9 + k];
#pragma unroll
            for (int p = 0; p < 4; ++p)
#pragma unroll
                for (int ky = 0; ky < 3; ++ky)
#pragma unroll
                    for (int kx = 0; kx < 3; ++kx)
                        acc[c][p] = fmaf(wr[ky * 3 + kx], xv[ky][p + kx], acc[c][p]);
        }
        __syncthreads();
    }

    const int oy = oy0 + th;
    const int oxb = ox0 + tw * 4;
#pragma unroll
    for (int c = 0; c < CO_PER; ++c) {
        float4 v = make_float4(acc[c][0], acc[c][1], acc[c][2], acc[c][3]);
        *reinterpret_cast<float4*>(
            &out[(((size_t)b * 64 + co0 + c) * 160 + oy) * 160 + oxb]) = v;
    }
}

extern "C" void kernel_launch(void* const* d_in, const int* in_sizes, int n_in,
                              void* d_out, int out_size) {
    const float* x = (const float*)d_in[0];
    const float* w = (const float*)d_in[1];
    float* out = (float*)d_out;
    (void)in_sizes; (void)n_in; (void)out_size;

    dim3 grid(160 / TILE_W, 160 / TILE_H, 16 * (64 / CO_PER));  // 5 x 5 x 128
    dim3 block(256);
    dconv_kernel<<<grid, block>>>(x, w, out);
}